// round 9
// baseline (speedup 1.0000x reference)
#include <cuda_runtime.h>

#define NN 100000
#define CH 128
#define NE 1600000
#define OC 64
#define OUT_ELEMS (2LL * NN * OC)   // 12,800,000
#define HALF_OFF  (OUT_ELEMS / 2)   // 6,400,000

// Scratch (allocation-free rule: __device__ globals).
// RULE (the 8-round bug): these symbols are ONLY referenced inside device
// code. They are NEVER passed as kernel arguments from host code — host
// code sees the host shadow symbol (valid under GB300 ATS, silently wrong).
__device__ float g_h0[(size_t)NN * CH];   // x@W1, then h = relu(...) in-place
__device__ float g_agg[(size_t)NN * CH];  // aggregation buffer (both layers)
__device__ float g_dinv[NN];              // deg then rsqrt(deg)
__device__ float g_W2[CH * CH];           // [W_mu | W_ls] packed, row-major [128 in][128 out]
__device__ float g_b2[CH];                // [b_mu | b_ls]
__device__ int   g_eidx[2 * NE];          // canonical int32 edge index
__device__ unsigned int g_orflag;         // OR of odd int32 words (0 -> int64 input)

// ---------------- diagnostic: deliberate crash (distinct harness error text) ----------------
__global__ void crash_kernel() {
    *((volatile int*)0) = 1;   // signals out_size mismatch
}

// ---------------- init: zero dinv + orflag ----------------
__global__ void init_kernel() {
    long long stride = (long long)gridDim.x * blockDim.x;
    long long i0 = (long long)blockIdx.x * blockDim.x + threadIdx.x;
    if (i0 == 0) g_orflag = 0u;
    for (long long i = i0; i < NN; i += stride) g_dinv[i] = 0.f;
}

// ---------------- edge-index dtype detect + convert ----------------
// OR-reduce odd int32 words of first 2*NE words. int64 data (vals < 2^31)
// has zero high-halves there; int32 data has random indices -> nonzero.
__global__ void detect_kernel(const unsigned int* __restrict__ ei32) {
    unsigned int acc = 0;
    long long stride = (long long)gridDim.x * blockDim.x;
    for (long long i = (long long)blockIdx.x * blockDim.x + threadIdx.x; i < NE; i += stride)
        acc |= ei32[2 * i + 1];
    #pragma unroll
    for (int o = 16; o > 0; o >>= 1) acc |= __shfl_down_sync(0xffffffffu, acc, o);
    if ((threadIdx.x & 31) == 0 && acc) atomicOr(&g_orflag, acc);
}

__global__ void convert_kernel(const void* __restrict__ ei) {
    long long stride = (long long)gridDim.x * blockDim.x;
    for (long long i = (long long)blockIdx.x * blockDim.x + threadIdx.x; i < 2 * (long long)NE; i += stride) {
        int v;
        if (g_orflag == 0u) v = (int)((const long long*)ei)[i];   // int64 input
        else                v = ((const int*)ei)[i];              // int32 input
        g_eidx[i] = v;
    }
}

// ---------------- degree / dinv ----------------
__global__ void deg_kernel() {
    long long stride = (long long)gridDim.x * blockDim.x;
    for (long long e = (long long)blockIdx.x * blockDim.x + threadIdx.x; e < NE; e += stride) {
        int d = g_eidx[NE + e];
        if ((unsigned)d < (unsigned)NN) atomicAdd(&g_dinv[d], 1.0f);
    }
}

__global__ void dinv_kernel() {
    long long stride = (long long)gridDim.x * blockDim.x;
    for (long long i = (long long)blockIdx.x * blockDim.x + threadIdx.x; i < NN; i += stride)
        g_dinv[i] = rsqrtf(g_dinv[i] + 1.0f);
}

// ---------------- zero helpers ----------------
__global__ void zero_agg_kernel() {
    long long stride = (long long)gridDim.x * blockDim.x;
    for (long long i = (long long)blockIdx.x * blockDim.x + threadIdx.x; i < (long long)NN * CH; i += stride)
        g_agg[i] = 0.f;
}

__global__ void zero_out_kernel(float* __restrict__ o) {
    long long stride = (long long)gridDim.x * blockDim.x;
    for (long long i = (long long)blockIdx.x * blockDim.x + threadIdx.x; i < OUT_ELEMS; i += stride)
        o[i] = 0.f;
}

// ---------------- edge scatter: g_agg[dst] += g_h0[src] * dinv[src]*dinv[dst] ----------------
// One warp per edge; each lane handles 4 channels with SCALAR atomics.
// Reads g_h0 / writes g_agg via device-side symbol references ONLY.
__global__ void scatter_kernel() {
    long long gt = (long long)blockIdx.x * blockDim.x + threadIdx.x;
    long long e = gt >> 5;
    int lane = (int)(gt & 31);
    if (e >= NE) return;
    int s = g_eidx[e];
    int d = g_eidx[NE + e];
    if ((unsigned)s >= (unsigned)NN || (unsigned)d >= (unsigned)NN) return;  // safety
    float norm = g_dinv[s] * g_dinv[d];
    const float* hr = g_h0 + (size_t)s * CH + lane * 4;
    float* ar = g_agg + (size_t)d * CH + lane * 4;
    atomicAdd(ar + 0, hr[0] * norm);
    atomicAdd(ar + 1, hr[1] * norm);
    atomicAdd(ar + 2, hr[2] * norm);
    atomicAdd(ar + 3, hr[3] * norm);
}

// ---------------- elementwise fusions ----------------
// g_h0 = relu(g_agg + g_h0*dinv^2 + b1)
__global__ void fuse1_kernel(const float* __restrict__ b1) {
    long long stride = (long long)gridDim.x * blockDim.x;
    for (long long i = (long long)blockIdx.x * blockDim.x + threadIdx.x; i < (long long)NN * CH; i += stride) {
        int node = (int)(i >> 7);
        int c = (int)(i & 127);
        float di = g_dinv[node];
        float v = g_agg[i] + g_h0[i] * di * di + b1[c];
        g_h0[i] = fmaxf(v, 0.f);
    }
}

// g_agg += g_h0*dinv^2
__global__ void fuse2_kernel() {
    long long stride = (long long)gridDim.x * blockDim.x;
    for (long long i = (long long)blockIdx.x * blockDim.x + threadIdx.x; i < (long long)NN * CH; i += stride) {
        int node = (int)(i >> 7);
        float di = g_dinv[node];
        g_agg[i] = g_agg[i] + g_h0[i] * di * di;
    }
}

// pack [W_mu | W_ls] and [b_mu | b_ls] into g_W2 / g_b2
__global__ void pack_kernel(const float* __restrict__ Wmu, const float* __restrict__ Wls,
                            const float* __restrict__ bmu, const float* __restrict__ bls) {
    int i = blockIdx.x * blockDim.x + threadIdx.x;
    if (i < CH * OC) {
        int r = i / OC, c = i % OC;
        g_W2[r * CH + c]      = Wmu[i];
        g_W2[r * CH + OC + c] = Wls[i];
    }
    if (i < OC) {
        g_b2[i]      = bmu[i];
        g_b2[OC + i] = bls[i];
    }
}

// ---------------- GEMM layer 1: g_h0[M x 128] = A[M x 128] @ B[128 x 128] ----------------
// A,B are HARNESS device pointers (legal as args). C = g_h0 via device symbol.
__global__ void gemm_l1_kernel(const float* __restrict__ A, const float* __restrict__ B) {
    __shared__ float Bs[128][64];
    __shared__ float As[4][128];
    int tid = threadIdx.x;
    int col = tid & 63;
    int rowg = tid >> 6;
    int yh = blockIdx.y;

    for (int k = rowg; k < 128; k += 4)
        Bs[k][col] = B[k * 128 + yh * 64 + col];
    __syncthreads();

    long long rowStep = 4LL * gridDim.x;
    for (long long r0 = (long long)blockIdx.x * 4; r0 < NN; r0 += rowStep) {
        __syncthreads();
        {
            int t = tid;
            #pragma unroll
            for (int q = 0; q < 2; q++, t += 256) {
                int rr = t >> 7;
                int cc = t & 127;
                long long gr = r0 + rr;
                As[rr][cc] = (gr < NN) ? A[(size_t)gr * 128 + cc] : 0.f;
            }
        }
        __syncthreads();
        long long gr = r0 + rowg;
        if (gr < NN) {
            float acc = 0.f;
            #pragma unroll 8
            for (int k = 0; k < 128; k++)
                acc = fmaf(As[rowg][k], Bs[k][col], acc);
            g_h0[(size_t)gr * 128 + yh * 64 + col] = acc;
        }
    }
}

// ---------------- GEMM layer 2: out = g_agg @ g_W2 + g_b2, split halves ----------------
// A = g_agg, B = g_W2, bias = g_b2 via device symbols. C = harness out pointer.
__global__ void gemm_l2_kernel(float* __restrict__ C) {
    __shared__ float Bs[128][64];
    __shared__ float As[4][128];
    int tid = threadIdx.x;
    int col = tid & 63;
    int rowg = tid >> 6;
    int yh = blockIdx.y;

    for (int k = rowg; k < 128; k += 4)
        Bs[k][col] = g_W2[k * 128 + yh * 64 + col];
    __syncthreads();

    long long rowStep = 4LL * gridDim.x;
    for (long long r0 = (long long)blockIdx.x * 4; r0 < NN; r0 += rowStep) {
        __syncthreads();
        {
            int t = tid;
            #pragma unroll
            for (int q = 0; q < 2; q++, t += 256) {
                int rr = t >> 7;
                int cc = t & 127;
                long long gr = r0 + rr;
                As[rr][cc] = (gr < NN) ? g_agg[(size_t)gr * 128 + cc] : 0.f;
            }
        }
        __syncthreads();
        long long gr = r0 + rowg;
        if (gr < NN) {
            float acc = g_b2[yh * 64 + col];
            #pragma unroll 8
            for (int k = 0; k < 128; k++)
                acc = fmaf(As[rowg][k], Bs[k][col], acc);
            long long idx = gr * 64 + col;
            if (yh == 0) C[idx] = acc;            // mu
            else         C[HALF_OFF + idx] = acc; // logstd
        }
    }
}

// ---------------- launch ----------------
extern "C" void kernel_launch(void* const* d_in, const int* in_sizes, int n_in,
                              void* d_out, int out_size) {
    // Identify inputs BY ELEMENT COUNT:
    //   x = 12,800,000; edge_index = 3,200,000 (elems) or 6,400,000 (i64 counted as i32);
    //   W1 = 16,384; b1 = 128; W_mu/W_ls = 8,192 (first = mu); b_mu/b_ls = 64 (first = mu).
    const float *x = 0, *W1 = 0, *b1 = 0, *Wmu = 0, *Wls = 0, *bmu = 0, *bls = 0;
    const void *ei = 0;
    for (int i = 0; i < n_in; i++) {
        long long s = in_sizes[i];
        if (s == 12800000LL)                        x  = (const float*)d_in[i];
        else if (s == 3200000LL || s == 6400000LL)  ei = d_in[i];
        else if (s == 16384LL)                      W1 = (const float*)d_in[i];
        else if (s == 128LL)                        b1 = (const float*)d_in[i];
        else if (s == 8192LL) { if (!Wmu) Wmu = (const float*)d_in[i]; else Wls = (const float*)d_in[i]; }
        else if (s == 64LL)   { if (!bmu) bmu = (const float*)d_in[i]; else bls = (const float*)d_in[i]; }
    }
    float* out = (float*)d_out;

    // SIGNAL A: identification failed -> launch NOTHING ("graph captured 0 nodes").
    if (!x || !ei || !W1 || !b1 || !Wmu || !Wls || !bmu || !bls) return;

    // SIGNAL B: out_size model wrong -> deliberate crash (distinct error text).
    if (!((long long)out_size == OUT_ELEMS || (long long)out_size == 4 * OUT_ELEMS)) {
        crash_kernel<<<1, 1>>>();
        return;
    }

    const int T = 256;
    dim3 gemmGrid(512, 2);

    // edge-index canonicalization + degrees
    init_kernel<<<400, T>>>();
    detect_kernel<<<256, T>>>((const unsigned int*)ei);
    convert_kernel<<<4096, T>>>(ei);
    deg_kernel<<<4096, T>>>();
    dinv_kernel<<<400, T>>>();

    // layer 1: g_h0 = x @ W1
    gemm_l1_kernel<<<gemmGrid, T>>>(x, W1);

    // agg1 = scatter(g_h0); g_h0 = relu(agg1 + g_h0*dinv^2 + b1)
    zero_agg_kernel<<<4096, T>>>();
    scatter_kernel<<<200000, T>>>();
    fuse1_kernel<<<4096, T>>>(b1);

    // layer 2 (linearity refactor): agg2 = scatter(h) + h*dinv^2, one packed GEMM
    zero_agg_kernel<<<4096, T>>>();
    scatter_kernel<<<200000, T>>>();
    fuse2_kernel<<<4096, T>>>();

    pack_kernel<<<(CH * OC + T - 1) / T, T>>>(Wmu, Wls, bmu, bls);
    zero_out_kernel<<<4096, T>>>(out);
    gemm_l2_kernel<<<gemmGrid, T>>>(out);
}

// round 10
// speedup vs baseline: 2.2122x; 2.2122x over previous
#include <cuda_runtime.h>

#define NN 100000
#define CH 128
#define NE 1600000
#define OC 64
#define OUT_ELEMS (2LL * NN * OC)   // 12,800,000
#define HALF_OFF  (OUT_ELEMS / 2)   // 6,400,000

// Scratch (allocation-free rule: __device__ globals).
// RULE (the 8-round bug): these symbols are ONLY referenced inside device
// code. NEVER passed as kernel arguments from host code (host shadow is
// valid under GB300 ATS and silently wrong).
__device__ float g_h0[(size_t)NN * CH];   // x@W1, then h = relu(...) in-place
__device__ float g_agg[(size_t)NN * CH];  // aggregation buffer (both layers)
__device__ float g_dinv[NN];              // deg then rsqrt(deg)
__device__ float g_W2[CH * CH];           // [W_mu | W_ls] packed row-major [128 in][128 out]
__device__ float g_b2[CH];                // [b_mu | b_ls]
__device__ int   g_eidx[2 * NE];          // canonical int32 edge index
__device__ unsigned int g_orflag;         // OR of odd int32 words (0 -> int64 input)

__global__ void crash_kernel() { *((volatile int*)0) = 1; }  // out_size mismatch signal

// ---------------- init: zero dinv + orflag ----------------
__global__ void init_kernel() {
    long long stride = (long long)gridDim.x * blockDim.x;
    long long i0 = (long long)blockIdx.x * blockDim.x + threadIdx.x;
    if (i0 == 0) g_orflag = 0u;
    for (long long i = i0; i < NN; i += stride) g_dinv[i] = 0.f;
}

// ---------------- edge-index dtype detect + convert ----------------
__global__ void detect_kernel(const unsigned int* __restrict__ ei32) {
    unsigned int acc = 0;
    long long stride = (long long)gridDim.x * blockDim.x;
    for (long long i = (long long)blockIdx.x * blockDim.x + threadIdx.x; i < NE; i += stride)
        acc |= ei32[2 * i + 1];
    #pragma unroll
    for (int o = 16; o > 0; o >>= 1) acc |= __shfl_down_sync(0xffffffffu, acc, o);
    if ((threadIdx.x & 31) == 0 && acc) atomicOr(&g_orflag, acc);
}

__global__ void convert_kernel(const void* __restrict__ ei) {
    long long stride = (long long)gridDim.x * blockDim.x;
    for (long long i = (long long)blockIdx.x * blockDim.x + threadIdx.x; i < 2 * (long long)NE; i += stride) {
        int v;
        if (g_orflag == 0u) v = (int)((const long long*)ei)[i];   // int64 input
        else                v = ((const int*)ei)[i];              // int32 input
        g_eidx[i] = v;
    }
}

// ---------------- degree / dinv ----------------
__global__ void deg_kernel() {
    long long stride = (long long)gridDim.x * blockDim.x;
    for (long long e = (long long)blockIdx.x * blockDim.x + threadIdx.x; e < NE; e += stride) {
        int d = g_eidx[NE + e];
        if ((unsigned)d < (unsigned)NN) atomicAdd(&g_dinv[d], 1.0f);
    }
}

__global__ void dinv_kernel() {
    long long stride = (long long)gridDim.x * blockDim.x;
    for (long long i = (long long)blockIdx.x * blockDim.x + threadIdx.x; i < NN; i += stride)
        g_dinv[i] = rsqrtf(g_dinv[i] + 1.0f);
}

// ---------------- zero agg (float4) ----------------
__global__ void zero_agg_kernel() {
    long long stride = (long long)gridDim.x * blockDim.x;
    for (long long i = (long long)blockIdx.x * blockDim.x + threadIdx.x; i < (long long)NN * CH / 4; i += stride)
        ((float4*)g_agg)[i] = make_float4(0.f, 0.f, 0.f, 0.f);
}

// ---------------- edge scatter: g_agg[dst] += g_h0[src]*dinv[s]*dinv[d] ----------------
// One warp per edge; one float4 per lane = 128 floats. RED.128 atomics.
__global__ void scatter_kernel() {
    long long gt = (long long)blockIdx.x * blockDim.x + threadIdx.x;
    long long e = gt >> 5;
    int lane = (int)(gt & 31);
    if (e >= NE) return;
    int s = g_eidx[e];
    int d = g_eidx[NE + e];
    if ((unsigned)s >= (unsigned)NN || (unsigned)d >= (unsigned)NN) return;
    float norm = g_dinv[s] * g_dinv[d];
    float4 v = ((const float4*)(g_h0 + (size_t)s * CH))[lane];
    v.x *= norm; v.y *= norm; v.z *= norm; v.w *= norm;
    atomicAdd(((float4*)(g_agg + (size_t)d * CH)) + lane, v);
}

// ---------------- elementwise fusions (float4) ----------------
// g_h0 = relu(g_agg + g_h0*dinv^2 + b1)
__global__ void fuse1_kernel(const float* __restrict__ b1) {
    long long stride = (long long)gridDim.x * blockDim.x;
    for (long long i = (long long)blockIdx.x * blockDim.x + threadIdx.x; i < (long long)NN * CH / 4; i += stride) {
        int node = (int)(i >> 5);           // CH/4 == 32
        int c4 = (int)(i & 31);
        float di = g_dinv[node];
        float d2 = di * di;
        float4 a = ((float4*)g_agg)[i];
        float4 h = ((float4*)g_h0)[i];
        float4 b = ((const float4*)b1)[c4];
        float4 r;
        r.x = fmaxf(fmaf(h.x, d2, a.x) + b.x, 0.f);
        r.y = fmaxf(fmaf(h.y, d2, a.y) + b.y, 0.f);
        r.z = fmaxf(fmaf(h.z, d2, a.z) + b.z, 0.f);
        r.w = fmaxf(fmaf(h.w, d2, a.w) + b.w, 0.f);
        ((float4*)g_h0)[i] = r;
    }
}

// g_agg += g_h0*dinv^2
__global__ void fuse2_kernel() {
    long long stride = (long long)gridDim.x * blockDim.x;
    for (long long i = (long long)blockIdx.x * blockDim.x + threadIdx.x; i < (long long)NN * CH / 4; i += stride) {
        int node = (int)(i >> 5);
        float di = g_dinv[node];
        float d2 = di * di;
        float4 a = ((float4*)g_agg)[i];
        float4 h = ((float4*)g_h0)[i];
        a.x = fmaf(h.x, d2, a.x);
        a.y = fmaf(h.y, d2, a.y);
        a.z = fmaf(h.z, d2, a.z);
        a.w = fmaf(h.w, d2, a.w);
        ((float4*)g_agg)[i] = a;
    }
}

// pack [W_mu | W_ls] and [b_mu | b_ls] into g_W2 / g_b2
__global__ void pack_kernel(const float* __restrict__ Wmu, const float* __restrict__ Wls,
                            const float* __restrict__ bmu, const float* __restrict__ bls) {
    int i = blockIdx.x * blockDim.x + threadIdx.x;
    if (i < CH * OC) {
        int r = i / OC, c = i % OC;
        g_W2[r * CH + c]      = Wmu[i];
        g_W2[r * CH + OC + c] = Wls[i];
    }
    if (i < OC) {
        g_b2[i]      = bmu[i];
        g_b2[OC + i] = bls[i];
    }
}

// ---------------- register-tiled SGEMM core ----------------
// 128x128 tile, BK=8, 256 threads, 8x8 microtile. A from gmem ptr; returns acc.
// Templated on the epilogue via MODE: 0 -> write g_h0 (device symbol);
// 1 -> bias g_b2 + split write to out (mu | logstd halves).
template <int MODE>
__device__ __forceinline__ void sgemm_core(const float* __restrict__ A,
                                           const float* __restrict__ Bsrc,
                                           float* __restrict__ Cout) {
    __shared__ float As[8][128];
    __shared__ float Bs[8][128];
    int tid = threadIdx.x;
    int tr = tid >> 4;        // 0..15
    int tc = tid & 15;        // 0..15
    long long rowBase = (long long)blockIdx.x * 128;

    float acc[8][8];
#pragma unroll
    for (int i = 0; i < 8; i++)
#pragma unroll
        for (int j = 0; j < 8; j++) acc[i][j] = 0.f;

    int arow = tid >> 1;            // 0..127
    int acol = (tid & 1) * 4;       // 0 or 4
    int brow = tid >> 5;            // 0..7
    int bcol = (tid & 31) * 4;      // 0..124
    long long gr0 = rowBase + arow;

    for (int kt = 0; kt < 128; kt += 8) {
        float4 av = make_float4(0.f, 0.f, 0.f, 0.f);
        if (gr0 < NN) av = *(const float4*)(A + (size_t)gr0 * 128 + kt + acol);
        As[acol + 0][arow] = av.x;
        As[acol + 1][arow] = av.y;
        As[acol + 2][arow] = av.z;
        As[acol + 3][arow] = av.w;
        float4 bv = *(const float4*)(Bsrc + (size_t)(kt + brow) * 128 + bcol);
        *(float4*)&Bs[brow][bcol] = bv;
        __syncthreads();
#pragma unroll
        for (int k = 0; k < 8; k++) {
            float a[8], b[8];
#pragma unroll
            for (int i = 0; i < 8; i++) a[i] = As[k][tr * 8 + i];
#pragma unroll
            for (int j = 0; j < 8; j++) b[j] = Bs[k][tc * 8 + j];
#pragma unroll
            for (int i = 0; i < 8; i++)
#pragma unroll
                for (int j = 0; j < 8; j++) acc[i][j] = fmaf(a[i], b[j], acc[i][j]);
        }
        __syncthreads();
    }

#pragma unroll
    for (int i = 0; i < 8; i++) {
        long long r = rowBase + tr * 8 + i;
        if (r >= NN) continue;
        if (MODE == 0) {
            float* cp = g_h0 + (size_t)r * 128 + tc * 8;
            *(float4*)(cp + 0) = make_float4(acc[i][0], acc[i][1], acc[i][2], acc[i][3]);
            *(float4*)(cp + 4) = make_float4(acc[i][4], acc[i][5], acc[i][6], acc[i][7]);
        } else {
            int c0 = tc * 8;                    // 0..120; never straddles 64
            float vb[8];
#pragma unroll
            for (int j = 0; j < 8; j++) vb[j] = acc[i][j] + g_b2[c0 + j];
            float* base;
            int cc;
            if (c0 < OC) { base = Cout;            cc = c0; }        // mu
            else         { base = Cout + HALF_OFF; cc = c0 - OC; }   // logstd
            float* cp = base + (size_t)r * OC + cc;
            *(float4*)(cp + 0) = make_float4(vb[0], vb[1], vb[2], vb[3]);
            *(float4*)(cp + 4) = make_float4(vb[4], vb[5], vb[6], vb[7]);
        }
    }
}

// layer 1: g_h0 = x @ W1   (x, W1 are harness pointers — legal args)
__global__ void gemm_l1_kernel(const float* __restrict__ A, const float* __restrict__ B) {
    sgemm_core<0>(A, B, nullptr);
}

// layer 2: out = g_agg @ g_W2 + g_b2 (split). A/B via device symbols inside.
__global__ void gemm_l2_kernel(float* __restrict__ Cout) {
    sgemm_core<1>(g_agg, g_W2, Cout);
}

// ---------------- launch ----------------
extern "C" void kernel_launch(void* const* d_in, const int* in_sizes, int n_in,
                              void* d_out, int out_size) {
    // Identify inputs BY ELEMENT COUNT (validated in R9):
    const float *x = 0, *W1 = 0, *b1 = 0, *Wmu = 0, *Wls = 0, *bmu = 0, *bls = 0;
    const void *ei = 0;
    for (int i = 0; i < n_in; i++) {
        long long s = in_sizes[i];
        if (s == 12800000LL)                        x  = (const float*)d_in[i];
        else if (s == 3200000LL || s == 6400000LL)  ei = d_in[i];
        else if (s == 16384LL)                      W1 = (const float*)d_in[i];
        else if (s == 128LL)                        b1 = (const float*)d_in[i];
        else if (s == 8192LL) { if (!Wmu) Wmu = (const float*)d_in[i]; else Wls = (const float*)d_in[i]; }
        else if (s == 64LL)   { if (!bmu) bmu = (const float*)d_in[i]; else bls = (const float*)d_in[i]; }
    }
    float* out = (float*)d_out;
    if (!x || !ei || !W1 || !b1 || !Wmu || !Wls || !bmu || !bls) return;  // Signal A
    if (!((long long)out_size == OUT_ELEMS || (long long)out_size == 4 * OUT_ELEMS)) {
        crash_kernel<<<1, 1>>>();  // Signal B
        return;
    }

    const int T = 256;
    int gemmBlocks = (NN + 127) / 128;   // 782

    // edge-index canonicalization + degrees
    init_kernel<<<400, T>>>();
    detect_kernel<<<256, T>>>((const unsigned int*)ei);
    convert_kernel<<<4096, T>>>(ei);
    deg_kernel<<<4096, T>>>();
    dinv_kernel<<<400, T>>>();

    // layer 1: g_h0 = x @ W1
    gemm_l1_kernel<<<gemmBlocks, T>>>(x, W1);

    // agg1 = scatter(g_h0); g_h0 = relu(agg1 + g_h0*dinv^2 + b1)
    zero_agg_kernel<<<4096, T>>>();
    scatter_kernel<<<200000, T>>>();
    fuse1_kernel<<<4096, T>>>(b1);

    // layer 2 (linearity refactor): agg2 = scatter(h) + h*dinv^2, one packed GEMM
    zero_agg_kernel<<<4096, T>>>();
    scatter_kernel<<<200000, T>>>();
    fuse2_kernel<<<4096, T>>>();

    pack_kernel<<<(CH * OC + T - 1) / T, T>>>(Wmu, Wls, bmu, bls);
    gemm_l2_kernel<<<gemmBlocks, T>>>(out);
}

// round 11
// speedup vs baseline: 3.9818x; 1.7999x over previous
#include <cuda_runtime.h>

#define NN 100000
#define CH 128
#define NE 1600000
#define OC 64
#define OUT_ELEMS (2LL * NN * OC)   // 12,800,000
#define HALF_OFF  (OUT_ELEMS / 2)   // 6,400,000
#define SCAN_BLK  391               // ceil(NN/256)

// Scratch (__device__ globals; NEVER passed as kernel args from host — GB300
// ATS makes the host-shadow silently valid-and-wrong).
__device__ float g_h0[(size_t)NN * CH];   // x@W1
__device__ float g_h1[(size_t)NN * CH];   // relu(gcn1)
__device__ float g_agg[(size_t)NN * CH];  // layer-2 aggregation
__device__ float g_dinv[NN];
__device__ float g_W2[CH * CH];           // [W_mu | W_ls]
__device__ float g_b2[CH];                // [b_mu | b_ls]
__device__ int   g_eidx[2 * NE];          // canonical int32 edge index
__device__ int   g_count[NN];             // in-degree histogram
__device__ int   g_rowstart[NN + 1];      // CSR row offsets
__device__ int   g_cursor[NN];            // fill cursors
__device__ int   g_csr_src[NE];           // CSR: src per edge, grouped by dst
__device__ int   g_partial[SCAN_BLK];     // scan partials
__device__ unsigned int g_orflag;

__global__ void crash_kernel() { *((volatile int*)0) = 1; }  // out_size mismatch signal

// ---------------- init: zero counts + orflag ----------------
__global__ void init_kernel() {
    long long stride = (long long)gridDim.x * blockDim.x;
    long long i0 = (long long)blockIdx.x * blockDim.x + threadIdx.x;
    if (i0 == 0) g_orflag = 0u;
    for (long long i = i0; i < NN; i += stride) g_count[i] = 0;
}

// ---------------- edge dtype detect ----------------
__global__ void detect_kernel(const unsigned int* __restrict__ ei32) {
    unsigned int acc = 0;
    long long stride = (long long)gridDim.x * blockDim.x;
    for (long long i = (long long)blockIdx.x * blockDim.x + threadIdx.x; i < NE; i += stride)
        acc |= ei32[2 * i + 1];
    #pragma unroll
    for (int o = 16; o > 0; o >>= 1) acc |= __shfl_down_sync(0xffffffffu, acc, o);
    if ((threadIdx.x & 31) == 0 && acc) atomicOr(&g_orflag, acc);
}

// ---------------- convert + fused dst histogram ----------------
__global__ void convert_hist_kernel(const void* __restrict__ ei) {
    long long stride = (long long)gridDim.x * blockDim.x;
    bool is64 = (g_orflag == 0u);
    for (long long i = (long long)blockIdx.x * blockDim.x + threadIdx.x; i < 2 * (long long)NE; i += stride) {
        int v = is64 ? (int)((const long long*)ei)[i] : ((const int*)ei)[i];
        g_eidx[i] = v;
        if (i >= NE && (unsigned)v < (unsigned)NN)   // dst half -> in-degree
            atomicAdd(&g_count[v], 1);
    }
}

// ---------------- dinv from counts ----------------
__global__ void dinv_kernel() {
    long long stride = (long long)gridDim.x * blockDim.x;
    for (long long i = (long long)blockIdx.x * blockDim.x + threadIdx.x; i < NN; i += stride)
        g_dinv[i] = rsqrtf((float)g_count[i] + 1.0f);
}

// ---------------- CSR build: block scan (3 stages) ----------------
__global__ void scan1_kernel() {   // per-block exclusive scan + block totals
    __shared__ int sh[256];
    int b = blockIdx.x, t = threadIdx.x;
    int i = b * 256 + t;
    int c = (i < NN) ? g_count[i] : 0;
    sh[t] = c;
    __syncthreads();
    // Hillis-Steele inclusive scan
    #pragma unroll
    for (int o = 1; o < 256; o <<= 1) {
        int v = (t >= o) ? sh[t - o] : 0;
        __syncthreads();
        sh[t] += v;
        __syncthreads();
    }
    if (i < NN) g_rowstart[i] = sh[t] - c;   // exclusive within block
    if (t == 255) g_partial[b] = sh[t];
}

__global__ void scan2_kernel() {   // serial scan of 391 partials (1 thread)
    if (threadIdx.x == 0 && blockIdx.x == 0) {
        int run = 0;
        for (int b = 0; b < SCAN_BLK; b++) {
            int v = g_partial[b];
            g_partial[b] = run;
            run += v;
        }
        g_rowstart[NN] = run;   // == NE for valid data
    }
}

__global__ void scan3_kernel() {   // add block base; init cursors
    int b = blockIdx.x, t = threadIdx.x;
    int i = b * 256 + t;
    if (i < NN) {
        int rs = g_rowstart[i] + g_partial[b];
        g_rowstart[i] = rs;
        g_cursor[i] = rs;
    }
}

// ---------------- CSR fill ----------------
__global__ void fill_kernel() {
    long long stride = (long long)gridDim.x * blockDim.x;
    for (long long e = (long long)blockIdx.x * blockDim.x + threadIdx.x; e < NE; e += stride) {
        int s = g_eidx[e];
        int d = g_eidx[NE + e];
        if ((unsigned)s >= (unsigned)NN || (unsigned)d >= (unsigned)NN) continue;
        int pos = atomicAdd(&g_cursor[d], 1);
        g_csr_src[pos] = s;
    }
}

// ---------------- pull aggregation: warp per node ----------------
// agg[d] = dinv[d] * Sum_{s in in(d)} dinv[s]*H[s]  +  dinv[d]^2 * H[d]
// LAYER==1: += b1, relu, write g_h1 (reads g_h0).
// LAYER==2: write g_agg raw (reads g_h1); bias added in gemm_l2.
template <int LAYER>
__global__ void pull_kernel(const float* __restrict__ b1) {
    long long gt = (long long)blockIdx.x * blockDim.x + threadIdx.x;
    int n = (int)(gt >> 5);
    int lane = (int)(gt & 31);
    if (n >= NN) return;
    const float* H = (LAYER == 1) ? g_h0 : g_h1;
    int row = g_rowstart[n];
    int end = g_rowstart[n + 1];
    float4 acc = make_float4(0.f, 0.f, 0.f, 0.f);
    #pragma unroll 2
    for (int e = row; e < end; e++) {
        int s = g_csr_src[e];                     // broadcast load
        float ws = g_dinv[s];                     // broadcast load
        float4 v = ((const float4*)(H + (size_t)s * CH))[lane];
        acc.x = fmaf(ws, v.x, acc.x);
        acc.y = fmaf(ws, v.y, acc.y);
        acc.z = fmaf(ws, v.z, acc.z);
        acc.w = fmaf(ws, v.w, acc.w);
    }
    float dd = g_dinv[n];
    float4 hd = ((const float4*)(H + (size_t)n * CH))[lane];
    float4 r;
    r.x = dd * acc.x + dd * dd * hd.x;
    r.y = dd * acc.y + dd * dd * hd.y;
    r.z = dd * acc.z + dd * dd * hd.z;
    r.w = dd * acc.w + dd * dd * hd.w;
    if (LAYER == 1) {
        float4 b = ((const float4*)b1)[lane];
        r.x = fmaxf(r.x + b.x, 0.f);
        r.y = fmaxf(r.y + b.y, 0.f);
        r.z = fmaxf(r.z + b.z, 0.f);
        r.w = fmaxf(r.w + b.w, 0.f);
        ((float4*)(g_h1 + (size_t)n * CH))[lane] = r;
    } else {
        ((float4*)(g_agg + (size_t)n * CH))[lane] = r;
    }
}

// ---------------- pack [W_mu|W_ls], [b_mu|b_ls] ----------------
__global__ void pack_kernel(const float* __restrict__ Wmu, const float* __restrict__ Wls,
                            const float* __restrict__ bmu, const float* __restrict__ bls) {
    int i = blockIdx.x * blockDim.x + threadIdx.x;
    if (i < CH * OC) {
        int r = i / OC, c = i % OC;
        g_W2[r * CH + c]      = Wmu[i];
        g_W2[r * CH + OC + c] = Wls[i];
    }
    if (i < OC) {
        g_b2[i]      = bmu[i];
        g_b2[OC + i] = bls[i];
    }
}

// ---------------- register-tiled SGEMM (128x128 tile, BK=8, 8x8 micro) ----------------
template <int MODE>
__device__ __forceinline__ void sgemm_core(const float* __restrict__ A,
                                           const float* __restrict__ Bsrc,
                                           float* __restrict__ Cout) {
    __shared__ float As[8][128];
    __shared__ float Bs[8][128];
    int tid = threadIdx.x;
    int tr = tid >> 4;
    int tc = tid & 15;
    long long rowBase = (long long)blockIdx.x * 128;

    float acc[8][8];
#pragma unroll
    for (int i = 0; i < 8; i++)
#pragma unroll
        for (int j = 0; j < 8; j++) acc[i][j] = 0.f;

    int arow = tid >> 1;
    int acol = (tid & 1) * 4;
    int brow = tid >> 5;
    int bcol = (tid & 31) * 4;
    long long gr0 = rowBase + arow;

    for (int kt = 0; kt < 128; kt += 8) {
        float4 av = make_float4(0.f, 0.f, 0.f, 0.f);
        if (gr0 < NN) av = *(const float4*)(A + (size_t)gr0 * 128 + kt + acol);
        As[acol + 0][arow] = av.x;
        As[acol + 1][arow] = av.y;
        As[acol + 2][arow] = av.z;
        As[acol + 3][arow] = av.w;
        float4 bv = *(const float4*)(Bsrc + (size_t)(kt + brow) * 128 + bcol);
        *(float4*)&Bs[brow][bcol] = bv;
        __syncthreads();
#pragma unroll
        for (int k = 0; k < 8; k++) {
            float a[8], b[8];
#pragma unroll
            for (int i = 0; i < 8; i++) a[i] = As[k][tr * 8 + i];
#pragma unroll
            for (int j = 0; j < 8; j++) b[j] = Bs[k][tc * 8 + j];
#pragma unroll
            for (int i = 0; i < 8; i++)
#pragma unroll
                for (int j = 0; j < 8; j++) acc[i][j] = fmaf(a[i], b[j], acc[i][j]);
        }
        __syncthreads();
    }

#pragma unroll
    for (int i = 0; i < 8; i++) {
        long long r = rowBase + tr * 8 + i;
        if (r >= NN) continue;
        if (MODE == 0) {
            float* cp = g_h0 + (size_t)r * 128 + tc * 8;
            *(float4*)(cp + 0) = make_float4(acc[i][0], acc[i][1], acc[i][2], acc[i][3]);
            *(float4*)(cp + 4) = make_float4(acc[i][4], acc[i][5], acc[i][6], acc[i][7]);
        } else {
            int c0 = tc * 8;
            float vb[8];
#pragma unroll
            for (int j = 0; j < 8; j++) vb[j] = acc[i][j] + g_b2[c0 + j];
            float* base;
            int cc;
            if (c0 < OC) { base = Cout;            cc = c0; }
            else         { base = Cout + HALF_OFF; cc = c0 - OC; }
            float* cp = base + (size_t)r * OC + cc;
            *(float4*)(cp + 0) = make_float4(vb[0], vb[1], vb[2], vb[3]);
            *(float4*)(cp + 4) = make_float4(vb[4], vb[5], vb[6], vb[7]);
        }
    }
}

__global__ void gemm_l1_kernel(const float* __restrict__ A, const float* __restrict__ B) {
    sgemm_core<0>(A, B, nullptr);        // g_h0 = x @ W1
}
__global__ void gemm_l2_kernel(float* __restrict__ Cout) {
    sgemm_core<1>(g_agg, g_W2, Cout);    // out = g_agg @ g_W2 + g_b2 (split)
}

// ---------------- launch ----------------
extern "C" void kernel_launch(void* const* d_in, const int* in_sizes, int n_in,
                              void* d_out, int out_size) {
    const float *x = 0, *W1 = 0, *b1 = 0, *Wmu = 0, *Wls = 0, *bmu = 0, *bls = 0;
    const void *ei = 0;
    for (int i = 0; i < n_in; i++) {
        long long s = in_sizes[i];
        if (s == 12800000LL)                        x  = (const float*)d_in[i];
        else if (s == 3200000LL || s == 6400000LL)  ei = d_in[i];
        else if (s == 16384LL)                      W1 = (const float*)d_in[i];
        else if (s == 128LL)                        b1 = (const float*)d_in[i];
        else if (s == 8192LL) { if (!Wmu) Wmu = (const float*)d_in[i]; else Wls = (const float*)d_in[i]; }
        else if (s == 64LL)   { if (!bmu) bmu = (const float*)d_in[i]; else bls = (const float*)d_in[i]; }
    }
    float* out = (float*)d_out;
    if (!x || !ei || !W1 || !b1 || !Wmu || !Wls || !bmu || !bls) return;  // Signal A
    if (!((long long)out_size == OUT_ELEMS || (long long)out_size == 4 * OUT_ELEMS)) {
        crash_kernel<<<1, 1>>>();  // Signal B
        return;
    }

    const int T = 256;
    int gemmBlocks = (NN + 127) / 128;       // 782
    int pullBlocks = (NN * 32 + T - 1) / T;  // 12500

    // canonicalize edges + degree histogram
    init_kernel<<<400, T>>>();
    detect_kernel<<<256, T>>>((const unsigned int*)ei);
    convert_hist_kernel<<<4096, T>>>(ei);
    dinv_kernel<<<400, T>>>();

    // CSR build (by dst)
    scan1_kernel<<<SCAN_BLK, T>>>();
    scan2_kernel<<<1, 32>>>();
    scan3_kernel<<<SCAN_BLK, T>>>();
    fill_kernel<<<4096, T>>>();

    // layer 1: g_h0 = x @ W1 ; g_h1 = relu(pull(g_h0) + b1)
    gemm_l1_kernel<<<gemmBlocks, T>>>(x, W1);
    pull_kernel<1><<<pullBlocks, T>>>(b1);

    // layer 2: g_agg = pull(g_h1) ; out = g_agg @ [W_mu|W_ls] + [b_mu|b_ls]
    pull_kernel<2><<<pullBlocks, T>>>(nullptr);
    pack_kernel<<<(CH * OC + T - 1) / T, T>>>(Wmu, Wls, bmu, bls);
    gemm_l2_kernel<<<gemmBlocks, T>>>(out);
}